// round 3
// baseline (speedup 1.0000x reference)
#include <cuda_runtime.h>
#include <cstdint>

#define BSZ   1024
#define LSEQ  200
#define CCH   80
#define OOUT  30
#define ROWS_TOT (BSZ * LSEQ)      // 204800
#define NCOL  240                  // C*W
#define KDIM  300
#define BM    128
#define BK    32
#define KPAD  36                   // padded smem row (floats), 16B-aligned, conflict-free
#define NCHUNK 10                  // ceil(300/32) -> K padded to 320 (zero-fill)
#define NSTAGE 3
#define NCTA  1626                 // ceil((ROWS_TOT-2)/126)
#define A_ST_FLOATS (BM * KPAD)        // 4608
#define B_ST_FLOATS (NCOL * KPAD)      // 8640
#define ST_FLOATS   (A_ST_FLOATS + B_ST_FLOATS)   // 13248
#define SMEM_DYN    (NSTAGE * ST_FLOATS * 4)      // 158976 B (>= D staging 124928)
#define DSS   244                  // D staging row stride (floats)

__device__ int g_h[2][BSZ * CCH];  // relu(max(conv)) as float-bits; zeroed each call

// ---------------- PTX helpers ----------------
__device__ __forceinline__ uint32_t smem_u32(const void* p) {
    uint32_t a;
    asm("{ .reg .u64 t; cvta.to.shared.u64 t, %1; cvt.u32.u64 %0, t; }" : "=r"(a) : "l"(p));
    return a;
}
__device__ __forceinline__ void cpa16(uint32_t dst, const void* src, int srcbytes) {
    asm volatile("cp.async.cg.shared.global [%0], [%1], 16, %2;"
                 :: "r"(dst), "l"(src), "r"(srcbytes) : "memory");
}
#define CP_COMMIT() asm volatile("cp.async.commit_group;" ::: "memory")
#define CP_WAIT2()  asm volatile("cp.async.wait_group 2;" ::: "memory")

__device__ __forceinline__ uint32_t t32(float f) {  // fp32 -> tf32, round-to-nearest
    uint32_t u;
    asm("cvt.rna.tf32.f32 %0, %1;" : "=r"(u) : "f"(f));
    return u;
}
__device__ __forceinline__ void mma8(float* d, const uint32_t* a, uint32_t b0, uint32_t b1) {
    asm volatile("mma.sync.aligned.m16n8k8.row.col.f32.tf32.tf32.f32 "
                 "{%0,%1,%2,%3}, {%4,%5,%6,%7}, {%8,%9}, {%0,%1,%2,%3};"
                 : "+f"(d[0]), "+f"(d[1]), "+f"(d[2]), "+f"(d[3])
                 : "r"(a[0]), "r"(a[1]), "r"(a[2]), "r"(a[3]), "r"(b0), "r"(b1));
}

// ---------------- stage loader ----------------
__device__ __forceinline__ void load_stage(char* sm, int s, const float* __restrict__ X,
                                           const float* __restrict__ Wt, int r0, int c) {
    float* As = (float*)sm + s * ST_FLOATS;
    float* Bs = As + A_ST_FLOATS;
    const int tid = threadIdx.x;
    const int kbase = c * BK;
    #pragma unroll
    for (int it = 0; it < 4; it++) {               // A: 128 rows x 8 vec4
        const int idx = tid + it * 256;
        const int row = idx >> 3, v = idx & 7;
        const int col = kbase + v * 4;
        const long grow = (long)r0 + row;
        const bool ok = (col < KDIM) & (grow < ROWS_TOT);
        const float* src = ok ? (X + grow * KDIM + col) : X;
        cpa16(smem_u32(&As[row * KPAD + v * 4]), src, ok ? 16 : 0);
    }
    #pragma unroll
    for (int it = 0; it < 8; it++) {               // B: 240 rows x 8 vec4
        const int idx = tid + it * 256;
        if (idx < NCOL * 8) {
            const int row = idx >> 3, v = idx & 7;
            const int col = kbase + v * 4;
            const bool ok = col < KDIM;
            const float* src = ok ? (Wt + row * KDIM + col) : Wt;
            cpa16(smem_u32(&Bs[row * KPAD + v * 4]), src, ok ? 16 : 0);
        }
    }
}

// ---------------- kernels ----------------
__global__ void zero_kernel() {
    ((int*)g_h)[blockIdx.x * blockDim.x + threadIdx.x] = 0;
}

__global__ void __launch_bounds__(256, 1) gemm_conv_kernel(
    const float* __restrict__ x1, const float* __restrict__ x2,
    const float* __restrict__ w1, const float* __restrict__ w2,
    const float* __restrict__ b1, const float* __restrict__ b2)
{
    extern __shared__ char sm[];
    const int tid = threadIdx.x, wid = tid >> 5, lane = tid & 31;
    const int grp = lane >> 2, tig = lane & 3;
    const int warp_m = wid & 3, warp_n = wid >> 2;     // 4 x 2 warp grid
    const int sub = blockIdx.y;
    const float* X  = sub ? x2 : x1;
    const float* Wt = sub ? w2 : w1;
    const float* bc = sub ? b2 : b1;
    const int r0 = blockIdx.x * 126;

    float acc[2][15][4];
    #pragma unroll
    for (int mt = 0; mt < 2; mt++)
        #pragma unroll
        for (int nt = 0; nt < 15; nt++)
            #pragma unroll
            for (int k = 0; k < 4; k++) acc[mt][nt][k] = 0.f;

    load_stage(sm, 0, X, Wt, r0, 0); CP_COMMIT();
    load_stage(sm, 1, X, Wt, r0, 1); CP_COMMIT();

    for (int c = 0; c < NCHUNK; c++) {
        if (c + 2 < NCHUNK) load_stage(sm, (c + 2) % NSTAGE, X, Wt, r0, c + 2);
        CP_COMMIT();                                  // empty group ok -> fixed wait depth
        CP_WAIT2();
        __syncthreads();
        const float* As = (const float*)sm + (c % NSTAGE) * ST_FLOATS;
        const float* Bs = As + A_ST_FLOATS;
        #pragma unroll
        for (int ks = 0; ks < 4; ks++) {
            const int k0 = ks * 8;
            uint32_t a[2][4];
            #pragma unroll
            for (int mt = 0; mt < 2; mt++) {
                const int rb = warp_m * 32 + mt * 16;
                a[mt][0] = t32(As[(rb + grp)     * KPAD + k0 + tig]);
                a[mt][1] = t32(As[(rb + grp + 8) * KPAD + k0 + tig]);
                a[mt][2] = t32(As[(rb + grp)     * KPAD + k0 + tig + 4]);
                a[mt][3] = t32(As[(rb + grp + 8) * KPAD + k0 + tig + 4]);
            }
            #pragma unroll
            for (int nt = 0; nt < 15; nt++) {
                const int n = warp_n * 120 + nt * 8 + grp;
                const uint32_t b0 = t32(Bs[n * KPAD + k0 + tig]);
                const uint32_t bb = t32(Bs[n * KPAD + k0 + tig + 4]);
                mma8(acc[0][nt], a[0], b0, bb);
                mma8(acc[1][nt], a[1], b0, bb);
            }
        }
        __syncthreads();
    }

    // ---- stage D (128 x 240) into smem ----
    float* ds = (float*)sm;
    #pragma unroll
    for (int mt = 0; mt < 2; mt++)
        #pragma unroll
        for (int nt = 0; nt < 15; nt++) {
            const int rb = warp_m * 32 + mt * 16 + grp;
            const int n0 = warp_n * 120 + nt * 8 + tig * 2;
            *(float2*)&ds[rb * DSS + n0]       = make_float2(acc[mt][nt][0], acc[mt][nt][1]);
            *(float2*)&ds[(rb + 8) * DSS + n0] = make_float2(acc[mt][nt][2], acc[mt][nt][3]);
        }
    __syncthreads();

    // ---- 3-tap diagonal combine + bias + relu + segment max + atomicMax ----
    const int bA = r0 / LSEQ;
    #pragma unroll
    for (int cc = 0; cc < 10; cc++) {
        const int ch = wid * 10 + cc;
        const float bias = __ldg(&bc[ch]);
        float mA = 0.f, mB = 0.f;
        #pragma unroll
        for (int k = 0; k < 4; k++) {
            const int i = lane + 32 * k;
            if (i >= 126) continue;
            const int g = r0 + i;
            if (g + 2 >= ROWS_TOT) continue;
            if ((g % LSEQ) > (LSEQ - 3)) continue;
            float v = ds[i * DSS + 3 * ch] + ds[(i + 1) * DSS + 3 * ch + 1]
                    + ds[(i + 2) * DSS + 3 * ch + 2] + bias;
            v = fmaxf(v, 0.f);
            if (g / LSEQ == bA) mA = fmaxf(mA, v); else mB = fmaxf(mB, v);
        }
        #pragma unroll
        for (int off = 16; off; off >>= 1) {
            mA = fmaxf(mA, __shfl_xor_sync(0xffffffffu, mA, off));
            mB = fmaxf(mB, __shfl_xor_sync(0xffffffffu, mB, off));
        }
        if (lane == 0) {
            if (mA > 0.f) atomicMax(&g_h[sub][bA * CCH + ch], __float_as_int(mA));
            if (mB > 0.f && bA + 1 < BSZ)
                atomicMax(&g_h[sub][(bA + 1) * CCH + ch], __float_as_int(mB));
        }
    }
}

__global__ void finish_kernel(const float* __restrict__ wfc1, const float* __restrict__ bfc1,
                              const float* __restrict__ wfc2, const float* __restrict__ bfc2,
                              float* __restrict__ out)
{
    const int b = blockIdx.x, j = threadIdx.x;
    float p = 0.f;
    if (j < OOUT) {
        float s1 = bfc1[j], s2 = bfc2[j];
        const int* h1 = &g_h[0][b * CCH];
        const int* h2 = &g_h[1][b * CCH];
        #pragma unroll 8
        for (int c = 0; c < CCH; c++) {
            s1 += __int_as_float(h1[c]) * wfc1[j * CCH + c];
            s2 += __int_as_float(h2[c]) * wfc2[j * CCH + c];
        }
        p = fmaxf(s1, 0.f) * fmaxf(s2, 0.f);
    }
    #pragma unroll
    for (int off = 16; off; off >>= 1) p += __shfl_xor_sync(0xffffffffu, p, off);
    if (j == 0) out[b] = p;
}

// ---------------- host ----------------
extern "C" void kernel_launch(void* const* d_in, const int* in_sizes, int n_in,
                              void* d_out, int out_size) {
    static bool attr_set = false;
    if (!attr_set) {
        cudaFuncSetAttribute(gemm_conv_kernel,
                             cudaFuncAttributeMaxDynamicSharedMemorySize, SMEM_DYN);
        attr_set = true;
    }
    zero_kernel<<<160, 1024>>>();
    gemm_conv_kernel<<<dim3(NCTA, 2), 256, SMEM_DYN>>>(
        (const float*)d_in[0], (const float*)d_in[1],
        (const float*)d_in[2], (const float*)d_in[6],
        (const float*)d_in[3], (const float*)d_in[7]);
    finish_kernel<<<BSZ, 32>>>((const float*)d_in[4], (const float*)d_in[5],
                               (const float*)d_in[8], (const float*)d_in[9],
                               (float*)d_out);
}

// round 4
// speedup vs baseline: 1.0730x; 1.0730x over previous
#include <cuda_runtime.h>
#include <cstdint>

#define BSZ   1024
#define LSEQ  200
#define CCH   80
#define OOUT  30
#define ROWS_TOT (BSZ * LSEQ)      // 204800
#define NCOL  240                  // C*W
#define KDIM  300
#define BM    128
#define BK    32
#define KPAD  36                   // padded smem row (floats)
#define NCHUNK 10                  // K padded to 304 (last chunk: 2 k-steps)
#define NSTAGE 3
#define NCTA  1626                 // ceil((ROWS_TOT-2)/126)
#define NTHR  384
#define A_ST_FLOATS (BM * KPAD)        // 4608
#define B_ST_FLOATS (NCOL * KPAD)      // 8640
#define ST_FLOATS   (A_ST_FLOATS + B_ST_FLOATS)   // 13248
#define SMEM_DYN    (NSTAGE * ST_FLOATS * 4)      // 158976 B
#define DSS   244                  // D staging row stride (floats)

__device__ int g_h[2][BSZ * CCH];            // relu(max(conv)) as float bits
__device__ uint32_t g_wt[2][NCOL * KDIM];    // pre-rounded tf32 weights

// ---------------- PTX helpers ----------------
__device__ __forceinline__ uint32_t smem_u32(const void* p) {
    uint32_t a;
    asm("{ .reg .u64 t; cvta.to.shared.u64 t, %1; cvt.u32.u64 %0, t; }" : "=r"(a) : "l"(p));
    return a;
}
__device__ __forceinline__ void cpa16(uint32_t dst, const void* src, int srcbytes) {
    asm volatile("cp.async.cg.shared.global [%0], [%1], 16, %2;"
                 :: "r"(dst), "l"(src), "r"(srcbytes) : "memory");
}
#define CP_COMMIT() asm volatile("cp.async.commit_group;" ::: "memory")
#define CP_WAIT2()  asm volatile("cp.async.wait_group 2;" ::: "memory")

__device__ __forceinline__ uint32_t t32(float f) {  // fp32 -> tf32, round-to-nearest
    uint32_t u;
    asm("cvt.rna.tf32.f32 %0, %1;" : "=r"(u) : "f"(f));
    return u;
}
__device__ __forceinline__ void mma8(float* d, const uint32_t* a, uint32_t b0, uint32_t b1) {
    asm volatile("mma.sync.aligned.m16n8k8.row.col.f32.tf32.tf32.f32 "
                 "{%0,%1,%2,%3}, {%4,%5,%6,%7}, {%8,%9}, {%0,%1,%2,%3};"
                 : "+f"(d[0]), "+f"(d[1]), "+f"(d[2]), "+f"(d[3])
                 : "r"(a[0]), "r"(a[1]), "r"(a[2]), "r"(a[3]), "r"(b0), "r"(b1));
}

// ---------------- stage loader ----------------
__device__ __forceinline__ void load_stage(char* sm, int s, const float* __restrict__ X,
                                           const uint32_t* __restrict__ Wt, int r0, int c) {
    float* As = (float*)sm + s * ST_FLOATS;
    float* Bs = As + A_ST_FLOATS;
    const int tid = threadIdx.x;
    const int kbase = c * BK;
    #pragma unroll
    for (int it = 0; it < 3; it++) {               // A: 128 rows x 8 vec4 = 1024
        const int idx = tid + it * NTHR;
        if (idx < BM * 8) {
            const int row = idx >> 3, v = idx & 7;
            const int col = kbase + v * 4;
            const long grow = (long)r0 + row;
            const bool ok = (col < KDIM) & (grow < ROWS_TOT);
            const float* src = ok ? (X + grow * KDIM + col) : X;
            cpa16(smem_u32(&As[row * KPAD + v * 4]), src, ok ? 16 : 0);
        }
    }
    #pragma unroll
    for (int it = 0; it < 5; it++) {               // B: 240 rows x 8 vec4 = 1920
        const int idx = tid + it * NTHR;
        const int row = idx >> 3, v = idx & 7;
        const int col = kbase + v * 4;
        const bool ok = col < KDIM;
        const uint32_t* src = ok ? (Wt + row * KDIM + col) : Wt;
        cpa16(smem_u32(&Bs[row * KPAD + v * 4]), src, ok ? 16 : 0);
    }
}

// ---------------- kernels ----------------
__global__ void prep_kernel(const float* __restrict__ w1, const float* __restrict__ w2) {
    const int i = blockIdx.x * blockDim.x + threadIdx.x;   // 160*1024 = 163840
    ((int*)g_h)[i] = 0;                                    // exactly 2*1024*80
    if (i < NCOL * KDIM) {
        g_wt[0][i] = t32(w1[i]);
        g_wt[1][i] = t32(w2[i]);
    }
}

__global__ void __launch_bounds__(NTHR, 1) gemm_conv_kernel(
    const float* __restrict__ X, int sub, const float* __restrict__ bc)
{
    extern __shared__ char sm[];
    const int tid = threadIdx.x, wid = tid >> 5, lane = tid & 31;
    const int grp = lane >> 2, tig = lane & 3;
    const int warp_m = wid & 3, warp_n = wid >> 2;     // 4 x 3 warp grid
    const uint32_t* Wt = g_wt[sub];
    const int r0 = blockIdx.x * 126;

    float acc[2][10][4];
    #pragma unroll
    for (int mt = 0; mt < 2; mt++)
        #pragma unroll
        for (int nt = 0; nt < 10; nt++)
            #pragma unroll
            for (int k = 0; k < 4; k++) acc[mt][nt][k] = 0.f;

    load_stage(sm, 0, X, Wt, r0, 0); CP_COMMIT();
    load_stage(sm, 1, X, Wt, r0, 1); CP_COMMIT();

    for (int c = 0; c < NCHUNK; c++) {
        if (c + 2 < NCHUNK) load_stage(sm, (c + 2) % NSTAGE, X, Wt, r0, c + 2);
        CP_COMMIT();
        CP_WAIT2();
        __syncthreads();
        const float*    As = (const float*)sm + (c % NSTAGE) * ST_FLOATS;
        const uint32_t* Bs = (const uint32_t*)(As + A_ST_FLOATS);
        const int ksmax = (c == NCHUNK - 1) ? 2 : 4;   // real K = 300 <= 304
        #pragma unroll
        for (int ks = 0; ks < 4; ks++) {
            if (ks >= ksmax) break;
            const int k0 = ks * 8;
            uint32_t a[2][4];
            #pragma unroll
            for (int mt = 0; mt < 2; mt++) {
                const int rb = warp_m * 32 + mt * 16;
                a[mt][0] = t32(As[(rb + grp)     * KPAD + k0 + tig]);
                a[mt][1] = t32(As[(rb + grp + 8) * KPAD + k0 + tig]);
                a[mt][2] = t32(As[(rb + grp)     * KPAD + k0 + tig + 4]);
                a[mt][3] = t32(As[(rb + grp + 8) * KPAD + k0 + tig + 4]);
            }
            #pragma unroll
            for (int nt = 0; nt < 10; nt++) {
                const int n = warp_n * 80 + nt * 8 + grp;
                const uint32_t b0 = Bs[n * KPAD + k0 + tig];
                const uint32_t b1 = Bs[n * KPAD + k0 + tig + 4];
                mma8(acc[0][nt], a[0], b0, b1);
                mma8(acc[1][nt], a[1], b0, b1);
            }
        }
        __syncthreads();
    }

    // ---- stage D (128 x 240) into smem ----
    float* ds = (float*)sm;
    #pragma unroll
    for (int mt = 0; mt < 2; mt++)
        #pragma unroll
        for (int nt = 0; nt < 10; nt++) {
            const int rb = warp_m * 32 + mt * 16 + grp;
            const int n0 = warp_n * 80 + nt * 8 + tig * 2;
            *(float2*)&ds[rb * DSS + n0]       = make_float2(acc[mt][nt][0], acc[mt][nt][1]);
            *(float2*)&ds[(rb + 8) * DSS + n0] = make_float2(acc[mt][nt][2], acc[mt][nt][3]);
        }
    __syncthreads();

    // ---- 3-tap diagonal combine + bias + relu + segment max + atomicMax ----
    const int bA = r0 / LSEQ;
    for (int ch = wid; ch < CCH; ch += 12) {
        const float bias = __ldg(&bc[ch]);
        float mA = 0.f, mB = 0.f;
        #pragma unroll
        for (int k = 0; k < 4; k++) {
            const int i = lane + 32 * k;
            if (i >= 126) continue;
            const int g = r0 + i;
            if (g + 2 >= ROWS_TOT) continue;
            if ((g % LSEQ) > (LSEQ - 3)) continue;
            float v = ds[i * DSS + 3 * ch] + ds[(i + 1) * DSS + 3 * ch + 1]
                    + ds[(i + 2) * DSS + 3 * ch + 2] + bias;
            v = fmaxf(v, 0.f);
            if (g / LSEQ == bA) mA = fmaxf(mA, v); else mB = fmaxf(mB, v);
        }
        #pragma unroll
        for (int off = 16; off; off >>= 1) {
            mA = fmaxf(mA, __shfl_xor_sync(0xffffffffu, mA, off));
            mB = fmaxf(mB, __shfl_xor_sync(0xffffffffu, mB, off));
        }
        if (lane == 0) {
            if (mA > 0.f) atomicMax(&g_h[sub][bA * CCH + ch], __float_as_int(mA));
            if (mB > 0.f && bA + 1 < BSZ)
                atomicMax(&g_h[sub][(bA + 1) * CCH + ch], __float_as_int(mB));
        }
    }
}

__global__ void finish_kernel(const float* __restrict__ wfc1, const float* __restrict__ bfc1,
                              const float* __restrict__ wfc2, const float* __restrict__ bfc2,
                              float* __restrict__ out)
{
    const int b = blockIdx.x, j = threadIdx.x;
    float p = 0.f;
    if (j < OOUT) {
        float s1 = bfc1[j], s2 = bfc2[j];
        const int* h1 = &g_h[0][b * CCH];
        const int* h2 = &g_h[1][b * CCH];
        #pragma unroll 8
        for (int c = 0; c < CCH; c++) {
            s1 += __int_as_float(h1[c]) * wfc1[j * CCH + c];
            s2 += __int_as_float(h2[c]) * wfc2[j * CCH + c];
        }
        p = fmaxf(s1, 0.f) * fmaxf(s2, 0.f);
    }
    #pragma unroll
    for (int off = 16; off; off >>= 1) p += __shfl_xor_sync(0xffffffffu, p, off);
    if (j == 0) out[b] = p;
}

// ---------------- host ----------------
extern "C" void kernel_launch(void* const* d_in, const int* in_sizes, int n_in,
                              void* d_out, int out_size) {
    static bool attr_set = false;
    if (!attr_set) {
        cudaFuncSetAttribute(gemm_conv_kernel,
                             cudaFuncAttributeMaxDynamicSharedMemorySize, SMEM_DYN);
        attr_set = true;
    }
    prep_kernel<<<160, 1024>>>((const float*)d_in[2], (const float*)d_in[6]);
    gemm_conv_kernel<<<NCTA, NTHR, SMEM_DYN>>>((const float*)d_in[0], 0, (const float*)d_in[3]);
    gemm_conv_kernel<<<NCTA, NTHR, SMEM_DYN>>>((const float*)d_in[1], 1, (const float*)d_in[7]);
    finish_kernel<<<BSZ, 32>>>((const float*)d_in[4], (const float*)d_in[5],
                               (const float*)d_in[8], (const float*)d_in[9],
                               (float*)d_out);
}

// round 5
// speedup vs baseline: 1.3301x; 1.2396x over previous
#include <cuda_runtime.h>
#include <cuda_fp16.h>
#include <cstdint>

#define BSZ   1024
#define LSEQ  200
#define CCH   80
#define OOUT  30
#define ROWS_TOT (BSZ * LSEQ)      // 204800
#define NCOL  240                  // C*W
#define KDIM  300
#define KSTR  320                  // zero-padded K stride for fp16 W
#define BM    128
#define BK    32                   // K elems per chunk
#define KPAD  36                   // A smem row stride (floats)
#define BPAD  40                   // B smem row stride (halves) -> 80B rows
#define NCHUNK 10                  // K = 320 incl zero pad, uniform
#define NSTAGE 3
#define NCTA  1626                 // ceil((ROWS_TOT-2)/126)
#define NTHR  384
#define A_BYTES (BM * KPAD * 4)        // 18432
#define B_BYTES (NCOL * BPAD * 2)      // 19200
#define ST_BYTES (A_BYTES + B_BYTES)   // 37632
#define DSS   241
#define SMEM_DYN (BM * DSS * 4)        // 123392 >= 3*ST_BYTES = 112896

__device__ int    g_h[2][BSZ * CCH];      // relu(max(conv)) as float bits
__device__ __half g_wh[2][NCOL * KSTR];   // fp16 weights, K zero-padded to 320

// ---------------- PTX helpers ----------------
__device__ __forceinline__ uint32_t smem_u32(const void* p) {
    uint32_t a;
    asm("{ .reg .u64 t; cvta.to.shared.u64 t, %1; cvt.u32.u64 %0, t; }" : "=r"(a) : "l"(p));
    return a;
}
__device__ __forceinline__ void cpa16(uint32_t dst, const void* src, int srcbytes) {
    asm volatile("cp.async.cg.shared.global [%0], [%1], 16, %2;"
                 :: "r"(dst), "l"(src), "r"(srcbytes) : "memory");
}
#define CP_COMMIT() asm volatile("cp.async.commit_group;" ::: "memory")
#define CP_WAIT2()  asm volatile("cp.async.wait_group 2;" ::: "memory")

__device__ __forceinline__ uint32_t packh2(float lo, float hi) {
    uint32_t r;
    asm("cvt.rn.f16x2.f32 %0, %1, %2;" : "=r"(r) : "f"(hi), "f"(lo));
    return r;
}
__device__ __forceinline__ void ldsm4(uint32_t* r, uint32_t addr) {
    asm volatile("ldmatrix.sync.aligned.m8n8.x4.shared.b16 {%0,%1,%2,%3}, [%4];"
                 : "=r"(r[0]), "=r"(r[1]), "=r"(r[2]), "=r"(r[3]) : "r"(addr));
}
__device__ __forceinline__ void mma16(float* d, const uint32_t* a, uint32_t b0, uint32_t b1) {
    asm volatile("mma.sync.aligned.m16n8k16.row.col.f32.f16.f16.f32 "
                 "{%0,%1,%2,%3}, {%4,%5,%6,%7}, {%8,%9}, {%0,%1,%2,%3};"
                 : "+f"(d[0]), "+f"(d[1]), "+f"(d[2]), "+f"(d[3])
                 : "r"(a[0]), "r"(a[1]), "r"(a[2]), "r"(a[3]), "r"(b0), "r"(b1));
}

// ---------------- stage loader ----------------
__device__ __forceinline__ void load_stage(char* sm, int s, const float* __restrict__ X,
                                           const __half* __restrict__ Wh, int r0, int c) {
    const int tid = threadIdx.x;
    const int kbase = c * BK;
    float* As = (float*)(sm + s * ST_BYTES);
    __half* Bs = (__half*)(sm + s * ST_BYTES + A_BYTES);
    #pragma unroll
    for (int it = 0; it < 3; it++) {               // A: 128 rows x 8 vec4(f32) = 1024
        const int idx = tid + it * NTHR;
        if (idx < BM * 8) {
            const int row = idx >> 3, v = idx & 7;
            const int col = kbase + v * 4;
            const long grow = (long)r0 + row;
            const bool ok = (col < KDIM) & (grow < ROWS_TOT);
            const float* src = ok ? (X + grow * KDIM + col) : X;
            cpa16(smem_u32(&As[row * KPAD + v * 4]), src, ok ? 16 : 0);
        }
    }
    #pragma unroll
    for (int it = 0; it < 3; it++) {               // B: 240 rows x 4 vec8(f16) = 960
        const int idx = tid + it * NTHR;
        if (idx < NCOL * 4) {
            const int row = idx >> 2, v = idx & 3;
            cpa16(smem_u32(&Bs[row * BPAD + v * 8]), Wh + row * KSTR + kbase + v * 8, 16);
        }
    }
}

// ---------------- kernels ----------------
__global__ void prep_kernel(const float* __restrict__ w1, const float* __restrict__ w2) {
    const int i = blockIdx.x * blockDim.x + threadIdx.x;   // 160*1024 = 163840
    ((int*)g_h)[i] = 0;                                    // 2*1024*80 = 163840
    if (i < NCOL * KSTR) {
        const int row = i / KSTR, col = i % KSTR;
        const float v1 = (col < KDIM) ? w1[row * KDIM + col] : 0.f;
        const float v2 = (col < KDIM) ? w2[row * KDIM + col] : 0.f;
        g_wh[0][i] = __float2half_rn(v1);
        g_wh[1][i] = __float2half_rn(v2);
    }
}

__global__ void __launch_bounds__(NTHR, 1) gemm_conv_kernel(
    const float* __restrict__ X, int sub, const float* __restrict__ bc)
{
    extern __shared__ char sm[];
    const int tid = threadIdx.x, wid = tid >> 5, lane = tid & 31;
    const int grp = lane >> 2, tig = lane & 3;
    const int warp_m = wid & 3, warp_n = wid >> 2;     // 4 x 3 warp grid
    const __half* Wh = g_wh[sub];
    const int r0 = blockIdx.x * 126;

    float acc[2][10][4];
    #pragma unroll
    for (int mt = 0; mt < 2; mt++)
        #pragma unroll
        for (int nt = 0; nt < 10; nt++)
            #pragma unroll
            for (int k = 0; k < 4; k++) acc[mt][nt][k] = 0.f;

    // B-fragment ldmatrix lane address components (constant across loop)
    const int bmat = lane >> 3;
    const int brow_off = ((bmat & 2) << 2) + (lane & 7);   // + pair*16 + warp_n*80
    const int bk_off = (bmat & 1) << 3;                    // halves

    load_stage(sm, 0, X, Wh, r0, 0); CP_COMMIT();
    load_stage(sm, 1, X, Wh, r0, 1); CP_COMMIT();

    for (int c = 0; c < NCHUNK; c++) {
        if (c + 2 < NCHUNK) load_stage(sm, (c + 2) % NSTAGE, X, Wh, r0, c + 2);
        CP_COMMIT();
        CP_WAIT2();
        __syncthreads();
        const float* As = (const float*)(sm + (c % NSTAGE) * ST_BYTES);
        const uint32_t Bs_u32 = smem_u32(sm) + (c % NSTAGE) * ST_BYTES + A_BYTES;
        #pragma unroll
        for (int ks = 0; ks < 2; ks++) {
            const int k0 = ks * 16;                       // floats within chunk
            uint32_t a[2][4];
            #pragma unroll
            for (int mt = 0; mt < 2; mt++) {
                const int row = warp_m * 32 + mt * 16 + grp;
                const float2 p0 = *(const float2*)&As[row * KPAD + k0 + tig * 2];
                const float2 p1 = *(const float2*)&As[(row + 8) * KPAD + k0 + tig * 2];
                const float2 p2 = *(const float2*)&As[row * KPAD + k0 + 8 + tig * 2];
                const float2 p3 = *(const float2*)&As[(row + 8) * KPAD + k0 + 8 + tig * 2];
                a[mt][0] = packh2(p0.x, p0.y);
                a[mt][1] = packh2(p1.x, p1.y);
                a[mt][2] = packh2(p2.x, p2.y);
                a[mt][3] = packh2(p3.x, p3.y);
            }
            #pragma unroll
            for (int pair = 0; pair < 5; pair++) {
                const int brow = warp_n * 80 + pair * 16 + brow_off;
                const uint32_t baddr = Bs_u32 + (brow * BPAD + k0 + bk_off) * 2;
                uint32_t b[4];
                ldsm4(b, baddr);
                mma16(acc[0][2 * pair],     a[0], b[0], b[1]);
                mma16(acc[1][2 * pair],     a[1], b[0], b[1]);
                mma16(acc[0][2 * pair + 1], a[0], b[2], b[3]);
                mma16(acc[1][2 * pair + 1], a[1], b[2], b[3]);
            }
        }
        __syncthreads();
    }

    // ---- stage D (128 x 240) into smem ----
    float* ds = (float*)sm;
    #pragma unroll
    for (int mt = 0; mt < 2; mt++)
        #pragma unroll
        for (int nt = 0; nt < 10; nt++) {
            const int rb = warp_m * 32 + mt * 16 + grp;
            const int n0 = warp_n * 80 + nt * 8 + tig * 2;
            ds[rb * DSS + n0]           = acc[mt][nt][0];
            ds[rb * DSS + n0 + 1]       = acc[mt][nt][1];
            ds[(rb + 8) * DSS + n0]     = acc[mt][nt][2];
            ds[(rb + 8) * DSS + n0 + 1] = acc[mt][nt][3];
        }
    __syncthreads();

    // ---- 3-tap diagonal combine + bias + relu + segment max + atomicMax ----
    const int bA = r0 / LSEQ;
    for (int ch = wid; ch < CCH; ch += 12) {
        const float bias = __ldg(&bc[ch]);
        float mA = 0.f, mB = 0.f;
        #pragma unroll
        for (int k = 0; k < 4; k++) {
            const int i = lane + 32 * k;
            if (i >= 126) continue;
            const int g = r0 + i;
            if (g + 2 >= ROWS_TOT) continue;
            if ((g % LSEQ) > (LSEQ - 3)) continue;
            float v = ds[i * DSS + 3 * ch] + ds[(i + 1) * DSS + 3 * ch + 1]
                    + ds[(i + 2) * DSS + 3 * ch + 2] + bias;
            v = fmaxf(v, 0.f);
            if (g / LSEQ == bA) mA = fmaxf(mA, v); else mB = fmaxf(mB, v);
        }
        #pragma unroll
        for (int off = 16; off; off >>= 1) {
            mA = fmaxf(mA, __shfl_xor_sync(0xffffffffu, mA, off));
            mB = fmaxf(mB, __shfl_xor_sync(0xffffffffu, mB, off));
        }
        if (lane == 0) {
            if (mA > 0.f) atomicMax(&g_h[sub][bA * CCH + ch], __float_as_int(mA));
            if (mB > 0.f && bA + 1 < BSZ)
                atomicMax(&g_h[sub][(bA + 1) * CCH + ch], __float_as_int(mB));
        }
    }
}

__global__ void __launch_bounds__(128) finish_kernel(
    const float* __restrict__ wfc1, const float* __restrict__ bfc1,
    const float* __restrict__ wfc2, const float* __restrict__ bfc2,
    float* __restrict__ out)
{
    const int wid = threadIdx.x >> 5, j = threadIdx.x & 31;
    const int b = blockIdx.x * 4 + wid;
    float p = 0.f;
    if (j < OOUT) {
        float s1 = bfc1[j], s2 = bfc2[j];
        const int* h1 = &g_h[0][b * CCH];
        const int* h2 = &g_h[1][b * CCH];
        #pragma unroll 8
        for (int c = 0; c < CCH; c++) {
            s1 += __int_as_float(h1[c]) * wfc1[j * CCH + c];
            s2 += __int_as_float(h2[c]) * wfc2[j * CCH + c];
        }
        p = fmaxf(s1, 0.f) * fmaxf(s2, 0.f);
    }
    #pragma unroll
    for (int off = 16; off; off >>= 1) p += __shfl_xor_sync(0xffffffffu, p, off);
    if (j == 0) out[b] = p;
}

// ---------------- host ----------------
extern "C" void kernel_launch(void* const* d_in, const int* in_sizes, int n_in,
                              void* d_out, int out_size) {
    static bool attr_set = false;
    if (!attr_set) {
        cudaFuncSetAttribute(gemm_conv_kernel,
                             cudaFuncAttributeMaxDynamicSharedMemorySize, SMEM_DYN);
        attr_set = true;
    }
    prep_kernel<<<160, 1024>>>((const float*)d_in[2], (const float*)d_in[6]);
    gemm_conv_kernel<<<NCTA, NTHR, SMEM_DYN>>>((const float*)d_in[0], 0, (const float*)d_in[3]);
    gemm_conv_kernel<<<NCTA, NTHR, SMEM_DYN>>>((const float*)d_in[1], 1, (const float*)d_in[7]);
    finish_kernel<<<BSZ / 4, 128>>>((const float*)d_in[4], (const float*)d_in[5],
                                    (const float*)d_in[8], (const float*)d_in[9],
                                    (float*)d_out);
}

// round 6
// speedup vs baseline: 1.3467x; 1.0125x over previous
#include <cuda_runtime.h>
#include <cuda_fp16.h>
#include <cstdint>

#define BSZ   1024
#define LSEQ  200
#define CCH   80
#define OOUT  30
#define ROWS_TOT (BSZ * LSEQ)      // 204800
#define NCOL  240                  // C*W
#define KDIM  300
#define KSTR  320                  // zero-padded K stride for fp16 W
#define BM    128
#define BN    120                  // N per CTA (2 CTAs cover 240)
#define BK    32
#define KPAD  36                   // A smem row stride (floats)
#define BPAD  40                   // B smem row stride (halves)
#define NCHUNK 10
#define NSTAGE 3
#define NCTA  1626                 // M strips
#define NTHR  384
#define A_BYTES (BM * KPAD * 4)        // 18432
#define B_BYTES (BN * BPAD * 2)        // 9600
#define ST_BYTES (A_BYTES + B_BYTES)   // 28032
#define SMEM_DYN (NSTAGE * ST_BYTES)   // 84096 >= D staging 61952
#define DSS   121                      // D staging stride (floats, odd)

__device__ int    g_h[2][BSZ * CCH];
__device__ __half g_wh[2][NCOL * KSTR];

// ---------------- PTX helpers ----------------
__device__ __forceinline__ uint32_t smem_u32(const void* p) {
    uint32_t a;
    asm("{ .reg .u64 t; cvta.to.shared.u64 t, %1; cvt.u32.u64 %0, t; }" : "=r"(a) : "l"(p));
    return a;
}
__device__ __forceinline__ void cpa16(uint32_t dst, const void* src, int srcbytes) {
    asm volatile("cp.async.cg.shared.global [%0], [%1], 16, %2;"
                 :: "r"(dst), "l"(src), "r"(srcbytes) : "memory");
}
#define CP_COMMIT() asm volatile("cp.async.commit_group;" ::: "memory")
#define CP_WAIT1()  asm volatile("cp.async.wait_group 1;" ::: "memory")

__device__ __forceinline__ uint32_t packh2(float lo, float hi) {
    uint32_t r;
    asm("cvt.rn.f16x2.f32 %0, %1, %2;" : "=r"(r) : "f"(hi), "f"(lo));
    return r;
}
__device__ __forceinline__ void ldsm4(uint32_t* r, uint32_t addr) {
    asm volatile("ldmatrix.sync.aligned.m8n8.x4.shared.b16 {%0,%1,%2,%3}, [%4];"
                 : "=r"(r[0]), "=r"(r[1]), "=r"(r[2]), "=r"(r[3]) : "r"(addr));
}
__device__ __forceinline__ void ldsm2(uint32_t* r, uint32_t addr) {
    asm volatile("ldmatrix.sync.aligned.m8n8.x2.shared.b16 {%0,%1}, [%2];"
                 : "=r"(r[0]), "=r"(r[1]) : "r"(addr));
}
__device__ __forceinline__ void mma16(float* d, const uint32_t* a, uint32_t b0, uint32_t b1) {
    asm volatile("mma.sync.aligned.m16n8k16.row.col.f32.f16.f16.f32 "
                 "{%0,%1,%2,%3}, {%4,%5,%6,%7}, {%8,%9}, {%0,%1,%2,%3};"
                 : "+f"(d[0]), "+f"(d[1]), "+f"(d[2]), "+f"(d[3])
                 : "r"(a[0]), "r"(a[1]), "r"(a[2]), "r"(a[3]), "r"(b0), "r"(b1));
}

// ---------------- stage loader ----------------
__device__ __forceinline__ void load_stage(char* sm, int s, const float* __restrict__ X,
                                           const __half* __restrict__ Wh, int r0, int nbase, int c) {
    const int tid = threadIdx.x;
    const int kbase = c * BK;
    float* As = (float*)(sm + s * ST_BYTES);
    __half* Bs = (__half*)(sm + s * ST_BYTES + A_BYTES);
    #pragma unroll
    for (int it = 0; it < 3; it++) {               // A: 128 x 8 vec4 = 1024
        const int idx = tid + it * NTHR;
        if (idx < BM * 8) {
            const int row = idx >> 3, v = idx & 7;
            const int col = kbase + v * 4;
            const long grow = (long)r0 + row;
            const bool ok = (col < KDIM) & (grow < ROWS_TOT);
            const float* src = ok ? (X + grow * KDIM + col) : X;
            cpa16(smem_u32(&As[row * KPAD + v * 4]), src, ok ? 16 : 0);
        }
    }
    #pragma unroll
    for (int it = 0; it < 2; it++) {               // B: 120 x 4 vec8 = 480
        const int idx = tid + it * NTHR;
        if (idx < BN * 4) {
            const int row = idx >> 2, v = idx & 3;
            cpa16(smem_u32(&Bs[row * BPAD + v * 8]),
                  Wh + (nbase + row) * KSTR + kbase + v * 8, 16);
        }
    }
}

// ---------------- kernels ----------------
__global__ void prep_kernel(const float* __restrict__ w1, const float* __restrict__ w2) {
    const int i = blockIdx.x * blockDim.x + threadIdx.x;   // 163840
    ((int*)g_h)[i] = 0;
    if (i < NCOL * KSTR) {
        const int row = i / KSTR, col = i % KSTR;
        g_wh[0][i] = __float2half_rn((col < KDIM) ? w1[row * KDIM + col] : 0.f);
        g_wh[1][i] = __float2half_rn((col < KDIM) ? w2[row * KDIM + col] : 0.f);
    }
}

__global__ void __launch_bounds__(NTHR, 2) gemm_conv_kernel(
    const float* __restrict__ x1, const float* __restrict__ x2,
    const float* __restrict__ b1, const float* __restrict__ b2)
{
    extern __shared__ char sm[];
    const int tid = threadIdx.x, wid = tid >> 5, lane = tid & 31;
    const int grp = lane >> 2, tig = lane & 3;
    const int warp_m = wid & 3, warp_n = wid >> 2;   // 4M x 3N, warp tile 32x40
    const int sub = blockIdx.z;
    const int nbase = blockIdx.y * BN;               // 0 or 120
    const float* X  = sub ? x2 : x1;
    const float* bc = sub ? b2 : b1;
    const __half* Wh = g_wh[sub];
    const int r0 = blockIdx.x * 126;

    float acc[2][5][4];
    #pragma unroll
    for (int mt = 0; mt < 2; mt++)
        #pragma unroll
        for (int nt = 0; nt < 5; nt++)
            #pragma unroll
            for (int k = 0; k < 4; k++) acc[mt][nt][k] = 0.f;

    const int bmat = lane >> 3;
    const int brow_off4 = ((bmat & 2) << 2) + (lane & 7);
    const int bk_off4 = (bmat & 1) << 3;
    const int brow_off2 = lane & 7;                 // ldsm.x2: lanes 0-15 matter
    const int bk_off2 = (bmat & 1) << 3;

    load_stage(sm, 0, X, Wh, r0, nbase, 0); CP_COMMIT();
    load_stage(sm, 1, X, Wh, r0, nbase, 1); CP_COMMIT();

    for (int c = 0; c < NCHUNK; c++) {
        CP_WAIT1();
        __syncthreads();
        if (c + 2 < NCHUNK) load_stage(sm, (c + 2) % NSTAGE, X, Wh, r0, nbase, c + 2);
        CP_COMMIT();
        const float* As = (const float*)(sm + (c % NSTAGE) * ST_BYTES);
        const uint32_t Bs_u32 = smem_u32(sm) + (c % NSTAGE) * ST_BYTES + A_BYTES;
        #pragma unroll
        for (int ks = 0; ks < 2; ks++) {
            const int k0 = ks * 16;
            uint32_t a[2][4];
            #pragma unroll
            for (int mt = 0; mt < 2; mt++) {
                const int row = warp_m * 32 + mt * 16 + grp;
                const float2 p0 = *(const float2*)&As[row * KPAD + k0 + tig * 2];
                const float2 p1 = *(const float2*)&As[(row + 8) * KPAD + k0 + tig * 2];
                const float2 p2 = *(const float2*)&As[row * KPAD + k0 + 8 + tig * 2];
                const float2 p3 = *(const float2*)&As[(row + 8) * KPAD + k0 + 8 + tig * 2];
                a[mt][0] = packh2(p0.x, p0.y);
                a[mt][1] = packh2(p1.x, p1.y);
                a[mt][2] = packh2(p2.x, p2.y);
                a[mt][3] = packh2(p3.x, p3.y);
            }
            // n-tiles 0..3 via 2x ldsm.x4, n-tile 4 via ldsm.x2
            #pragma unroll
            for (int pair = 0; pair < 2; pair++) {
                const int brow = warp_n * 40 + pair * 16 + brow_off4;
                uint32_t b[4];
                ldsm4(b, Bs_u32 + (brow * BPAD + k0 + bk_off4) * 2);
                mma16(acc[0][2 * pair],     a[0], b[0], b[1]);
                mma16(acc[1][2 * pair],     a[1], b[0], b[1]);
                mma16(acc[0][2 * pair + 1], a[0], b[2], b[3]);
                mma16(acc[1][2 * pair + 1], a[1], b[2], b[3]);
            }
            {
                const int brow = warp_n * 40 + 32 + brow_off2;
                uint32_t b[2];
                ldsm2(b, Bs_u32 + (brow * BPAD + k0 + bk_off2) * 2);
                mma16(acc[0][4], a[0], b[0], b[1]);
                mma16(acc[1][4], a[1], b[0], b[1]);
            }
        }
    }
    __syncthreads();

    // ---- stage D (128 x 120) into smem ----
    float* ds = (float*)sm;
    #pragma unroll
    for (int mt = 0; mt < 2; mt++)
        #pragma unroll
        for (int nt = 0; nt < 5; nt++) {
            const int rb = warp_m * 32 + mt * 16 + grp;
            const int n0 = warp_n * 40 + nt * 8 + tig * 2;
            ds[rb * DSS + n0]           = acc[mt][nt][0];
            ds[rb * DSS + n0 + 1]       = acc[mt][nt][1];
            ds[(rb + 8) * DSS + n0]     = acc[mt][nt][2];
            ds[(rb + 8) * DSS + n0 + 1] = acc[mt][nt][3];
        }
    __syncthreads();

    // ---- 3-tap diagonal combine + bias + relu + segment max + atomicMax ----
    const int bA = r0 / LSEQ;
    const int chbase = blockIdx.y * 40;
    for (int cl = wid; cl < 40; cl += 12) {
        const int ch = chbase + cl;
        const float bias = __ldg(&bc[ch]);
        float mA = 0.f, mB = 0.f;
        #pragma unroll
        for (int k = 0; k < 4; k++) {
            const int i = lane + 32 * k;
            if (i >= 126) continue;
            const int g = r0 + i;
            if (g + 2 >= ROWS_TOT) continue;
            if ((g % LSEQ) > (LSEQ - 3)) continue;
            float v = ds[i * DSS + 3 * cl] + ds[(i + 1) * DSS + 3 * cl + 1]
                    + ds[(i + 2) * DSS + 3 * cl + 2] + bias;
            v = fmaxf(v, 0.f);
            if (g / LSEQ == bA) mA = fmaxf(mA, v); else mB = fmaxf(mB, v);
        }
        #pragma unroll
        for (int off = 16; off; off >>= 1) {
            mA = fmaxf(mA, __shfl_xor_sync(0xffffffffu, mA, off));
            mB = fmaxf(mB, __shfl_xor_sync(0xffffffffu, mB, off));
        }
        if (lane == 0) {
            if (mA > 0.f) atomicMax(&g_h[sub][bA * CCH + ch], __float_as_int(mA));
            if (mB > 0.f && bA + 1 < BSZ)
                atomicMax(&g_h[sub][(bA + 1) * CCH + ch], __float_as_int(mB));
        }
    }
}

__global__ void __launch_bounds__(128) finish_kernel(
    const float* __restrict__ wfc1, const float* __restrict__ bfc1,
    const float* __restrict__ wfc2, const float* __restrict__ bfc2,
    float* __restrict__ out)
{
    const int wid = threadIdx.x >> 5, j = threadIdx.x & 31;
    const int b = blockIdx.x * 4 + wid;
    float p = 0.f;
    if (j < OOUT) {
        float s1 = bfc1[j], s2 = bfc2[j];
        const int* h1 = &g_h[0][b * CCH];
        const int* h2 = &g_h[1][b * CCH];
        #pragma unroll 8
        for (int c = 0; c < CCH; c++) {
            s1 += __int_as_float(h1[c]) * wfc1[j * CCH + c];
            s2 += __int_as_float(h2[c]) * wfc2[j * CCH + c];
        }
        p = fmaxf(s1, 0.f) * fmaxf(s2, 0.f);
    }
    #pragma unroll
    for (int off = 16; off; off >>= 1) p += __shfl_xor_sync(0xffffffffu, p, off);
    if (j == 0) out[b] = p;
}

// ---------------- host ----------------
extern "C" void kernel_launch(void* const* d_in, const int* in_sizes, int n_in,
                              void* d_out, int out_size) {
    static bool attr_set = false;
    if (!attr_set) {
        cudaFuncSetAttribute(gemm_conv_kernel,
                             cudaFuncAttributeMaxDynamicSharedMemorySize, SMEM_DYN);
        attr_set = true;
    }
    prep_kernel<<<160, 1024>>>((const float*)d_in[2], (const float*)d_in[6]);
    gemm_conv_kernel<<<dim3(NCTA, 2, 2), NTHR, SMEM_DYN>>>(
        (const float*)d_in[0], (const float*)d_in[1],
        (const float*)d_in[3], (const float*)d_in[7]);
    finish_kernel<<<BSZ / 4, 128>>>((const float*)d_in[4], (const float*)d_in[5],
                                    (const float*)d_in[8], (const float*)d_in[9],
                                    (float*)d_out);
}

// round 7
// speedup vs baseline: 1.4133x; 1.0495x over previous
#include <cuda_runtime.h>
#include <cuda_fp16.h>
#include <cstdint>

#define BSZ   1024
#define LSEQ  200
#define CCH   80
#define OOUT  30
#define ROWS_TOT (BSZ * LSEQ)      // 204800
#define NCOL  240                  // C*W
#define KDIM  300
#define KSTR  320                  // zero-padded K stride for fp16 W
#define BM    128
#define BN    120                  // N per CTA (2 CTAs cover 240)
#define BK    32
#define KPAD  36                   // A smem row stride (floats)
#define BPAD  40                   // B smem row stride (halves)
#define NCHUNK 10                  // last chunk: 1 k-step -> K=304
#define NSTAGE 3
#define NCTA  1626                 // M strips
#define NTHR  384
#define A_BYTES (BM * KPAD * 4)        // 18432
#define B_BYTES (BN * BPAD * 2)        // 9600
#define ST_BYTES (A_BYTES + B_BYTES)   // 28032
#define SMEM_DYN (NSTAGE * ST_BYTES)   // 84096 >= D staging 61952
#define DSS   121                      // D staging stride (floats, odd)

__device__ int    g_h[2][BSZ * CCH];
__device__ __half g_wh[2][NCOL * KSTR];

// ---------------- PTX helpers ----------------
__device__ __forceinline__ uint32_t smem_u32(const void* p) {
    uint32_t a;
    asm("{ .reg .u64 t; cvta.to.shared.u64 t, %1; cvt.u32.u64 %0, t; }" : "=r"(a) : "l"(p));
    return a;
}
__device__ __forceinline__ void cpa16(uint32_t dst, const void* src, int srcbytes) {
    asm volatile("cp.async.cg.shared.global [%0], [%1], 16, %2;"
                 :: "r"(dst), "l"(src), "r"(srcbytes) : "memory");
}
#define CP_COMMIT() asm volatile("cp.async.commit_group;" ::: "memory")
#define CP_WAIT1()  asm volatile("cp.async.wait_group 1;" ::: "memory")

__device__ __forceinline__ uint32_t packh2(float lo, float hi) {
    uint32_t r;
    asm("cvt.rn.f16x2.f32 %0, %1, %2;" : "=r"(r) : "f"(hi), "f"(lo));
    return r;
}
__device__ __forceinline__ void ldsm4(uint32_t* r, uint32_t addr) {
    asm volatile("ldmatrix.sync.aligned.m8n8.x4.shared.b16 {%0,%1,%2,%3}, [%4];"
                 : "=r"(r[0]), "=r"(r[1]), "=r"(r[2]), "=r"(r[3]) : "r"(addr));
}
__device__ __forceinline__ void ldsm2(uint32_t* r, uint32_t addr) {
    asm volatile("ldmatrix.sync.aligned.m8n8.x2.shared.b16 {%0,%1}, [%2];"
                 : "=r"(r[0]), "=r"(r[1]) : "r"(addr));
}
// fp16-accumulator HMMA: {c0,c1} = 4 halves = rows {grp, grp+8} x cols {2t, 2t+1}
__device__ __forceinline__ void mma16h(uint32_t* c, const uint32_t* a, uint32_t b0, uint32_t b1) {
    asm volatile("mma.sync.aligned.m16n8k16.row.col.f16.f16.f16.f16 "
                 "{%0,%1}, {%2,%3,%4,%5}, {%6,%7}, {%0,%1};"
                 : "+r"(c[0]), "+r"(c[1])
                 : "r"(a[0]), "r"(a[1]), "r"(a[2]), "r"(a[3]), "r"(b0), "r"(b1));
}

// ---------------- stage loader ----------------
__device__ __forceinline__ void load_stage(char* sm, int s, const float* __restrict__ X,
                                           const __half* __restrict__ Wh, int r0, int nbase, int c) {
    const int tid = threadIdx.x;
    const int kbase = c * BK;
    float* As = (float*)(sm + s * ST_BYTES);
    __half* Bs = (__half*)(sm + s * ST_BYTES + A_BYTES);
    #pragma unroll
    for (int it = 0; it < 3; it++) {               // A: 128 x 8 vec4 = 1024
        const int idx = tid + it * NTHR;
        if (idx < BM * 8) {
            const int row = idx >> 3, v = idx & 7;
            const int col = kbase + v * 4;
            const long grow = (long)r0 + row;
            const bool ok = (col < KDIM) & (grow < ROWS_TOT);
            const float* src = ok ? (X + grow * KDIM + col) : X;
            cpa16(smem_u32(&As[row * KPAD + v * 4]), src, ok ? 16 : 0);
        }
    }
    #pragma unroll
    for (int it = 0; it < 2; it++) {               // B: 120 x 4 vec8 = 480
        const int idx = tid + it * NTHR;
        if (idx < BN * 4) {
            const int row = idx >> 2, v = idx & 3;
            cpa16(smem_u32(&Bs[row * BPAD + v * 8]),
                  Wh + (nbase + row) * KSTR + kbase + v * 8, 16);
        }
    }
}

// ---------------- kernels ----------------
__global__ void prep_kernel(const float* __restrict__ w1, const float* __restrict__ w2) {
    const int i = blockIdx.x * blockDim.x + threadIdx.x;   // 163840
    ((int*)g_h)[i] = 0;
    if (i < NCOL * KSTR) {
        const int row = i / KSTR, col = i % KSTR;
        g_wh[0][i] = __float2half_rn((col < KDIM) ? w1[row * KDIM + col] : 0.f);
        g_wh[1][i] = __float2half_rn((col < KDIM) ? w2[row * KDIM + col] : 0.f);
    }
}

__global__ void __launch_bounds__(NTHR, 2) gemm_conv_kernel(
    const float* __restrict__ x1, const float* __restrict__ x2,
    const float* __restrict__ b1, const float* __restrict__ b2)
{
    extern __shared__ char sm[];
    const int tid = threadIdx.x, wid = tid >> 5, lane = tid & 31;
    const int grp = lane >> 2, tig = lane & 3;
    const int warp_m = wid & 3, warp_n = wid >> 2;   // 4M x 3N, warp tile 32x40
    const int sub = blockIdx.z;
    const int nbase = blockIdx.y * BN;               // 0 or 120
    const float* X  = sub ? x2 : x1;
    const float* bc = sub ? b2 : b1;
    const __half* Wh = g_wh[sub];
    const int r0 = blockIdx.x * 126;

    uint32_t acc[2][5][2];                           // f16x2 accumulators
    #pragma unroll
    for (int mt = 0; mt < 2; mt++)
        #pragma unroll
        for (int nt = 0; nt < 5; nt++) {
            acc[mt][nt][0] = 0u; acc[mt][nt][1] = 0u;
        }

    const int bmat = lane >> 3;
    const int brow_off4 = ((bmat & 2) << 2) + (lane & 7);
    const int bk_off4 = (bmat & 1) << 3;
    const int brow_off2 = lane & 7;
    const int bk_off2 = (bmat & 1) << 3;

    load_stage(sm, 0, X, Wh, r0, nbase, 0); CP_COMMIT();
    load_stage(sm, 1, X, Wh, r0, nbase, 1); CP_COMMIT();

    for (int c = 0; c < NCHUNK; c++) {
        CP_WAIT1();
        __syncthreads();
        if (c + 2 < NCHUNK) load_stage(sm, (c + 2) % NSTAGE, X, Wh, r0, nbase, c + 2);
        CP_COMMIT();
        const float* As = (const float*)(sm + (c % NSTAGE) * ST_BYTES);
        const uint32_t Bs_u32 = smem_u32(sm) + (c % NSTAGE) * ST_BYTES + A_BYTES;
        const int ksmax = (c == NCHUNK - 1) ? 1 : 2;  // K = 304 total
        #pragma unroll
        for (int ks = 0; ks < 2; ks++) {
            if (ks >= ksmax) break;
            const int k0 = ks * 16;
            uint32_t a[2][4];
            #pragma unroll
            for (int mt = 0; mt < 2; mt++) {
                const int row = warp_m * 32 + mt * 16 + grp;
                const float2 p0 = *(const float2*)&As[row * KPAD + k0 + tig * 2];
                const float2 p1 = *(const float2*)&As[(row + 8) * KPAD + k0 + tig * 2];
                const float2 p2 = *(const float2*)&As[row * KPAD + k0 + 8 + tig * 2];
                const float2 p3 = *(const float2*)&As[(row + 8) * KPAD + k0 + 8 + tig * 2];
                a[mt][0] = packh2(p0.x, p0.y);
                a[mt][1] = packh2(p1.x, p1.y);
                a[mt][2] = packh2(p2.x, p2.y);
                a[mt][3] = packh2(p3.x, p3.y);
            }
            #pragma unroll
            for (int pair = 0; pair < 2; pair++) {
                const int brow = warp_n * 40 + pair * 16 + brow_off4;
                uint32_t b[4];
                ldsm4(b, Bs_u32 + (brow * BPAD + k0 + bk_off4) * 2);
                mma16h(acc[0][2 * pair],     a[0], b[0], b[1]);
                mma16h(acc[1][2 * pair],     a[1], b[0], b[1]);
                mma16h(acc[0][2 * pair + 1], a[0], b[2], b[3]);
                mma16h(acc[1][2 * pair + 1], a[1], b[2], b[3]);
            }
            {
                const int brow = warp_n * 40 + 32 + brow_off2;
                uint32_t b[2];
                ldsm2(b, Bs_u32 + (brow * BPAD + k0 + bk_off2) * 2);
                mma16h(acc[0][4], a[0], b[0], b[1]);
                mma16h(acc[1][4], a[1], b[0], b[1]);
            }
        }
    }
    __syncthreads();

    // ---- stage D (128 x 120) into smem (unpack f16x2 -> f32) ----
    float* ds = (float*)sm;
    #pragma unroll
    for (int mt = 0; mt < 2; mt++)
        #pragma unroll
        for (int nt = 0; nt < 5; nt++) {
            const int rb = warp_m * 32 + mt * 16 + grp;
            const int n0 = warp_n * 40 + nt * 8 + tig * 2;
            const float2 lo = __half22float2(*(__half2*)&acc[mt][nt][0]);
            const float2 hi = __half22float2(*(__half2*)&acc[mt][nt][1]);
            ds[rb * DSS + n0]           = lo.x;
            ds[rb * DSS + n0 + 1]       = lo.y;
            ds[(rb + 8) * DSS + n0]     = hi.x;
            ds[(rb + 8) * DSS + n0 + 1] = hi.y;
        }
    __syncthreads();

    // ---- 3-tap diagonal combine + bias + relu + segment max + atomicMax ----
    const int bA = r0 / LSEQ;
    const int chbase = blockIdx.y * 40;
    for (int cl = wid; cl < 40; cl += 12) {
        const int ch = chbase + cl;
        const float bias = __ldg(&bc[ch]);
        float mA = 0.f, mB = 0.f;
        #pragma unroll
        for (int k = 0; k < 4; k++) {
            const int i = lane + 32 * k;
            if (i >= 126) continue;
            const int g = r0 + i;
            if (g + 2 >= ROWS_TOT) continue;
            if ((g % LSEQ) > (LSEQ - 3)) continue;
            float v = ds[i * DSS + 3 * cl] + ds[(i + 1) * DSS + 3 * cl + 1]
                    + ds[(i + 2) * DSS + 3 * cl + 2] + bias;
            v = fmaxf(v, 0.f);
            if (g / LSEQ == bA) mA = fmaxf(mA, v); else mB = fmaxf(mB, v);
        }
        #pragma unroll
        for (int off = 16; off; off >>= 1) {
            mA = fmaxf(mA, __shfl_xor_sync(0xffffffffu, mA, off));
            mB = fmaxf(mB, __shfl_xor_sync(0xffffffffu, mB, off));
        }
        if (lane == 0) {
            if (mA > 0.f) atomicMax(&g_h[sub][bA * CCH + ch], __float_as_int(mA));
            if (mB > 0.f && bA + 1 < BSZ)
                atomicMax(&g_h[sub][(bA + 1) * CCH + ch], __float_as_int(mB));
        }
    }
}

__global__ void __launch_bounds__(256) finish_kernel(
    const float* __restrict__ wfc1, const float* __restrict__ bfc1,
    const float* __restrict__ wfc2, const float* __restrict__ bfc2,
    float* __restrict__ out)
{
    const int wid = threadIdx.x >> 5, j = threadIdx.x & 31;
    const int b = blockIdx.x * 8 + wid;
    float p = 0.f;
    if (j < OOUT) {
        float s1 = bfc1[j], s2 = bfc2[j];
        const int* h1 = &g_h[0][b * CCH];
        const int* h2 = &g_h[1][b * CCH];
        #pragma unroll 8
        for (int c = 0; c < CCH; c++) {
            s1 += __int_as_float(h1[c]) * wfc1[j * CCH + c];
            s2 += __int_as_float(h2[c]) * wfc2[j * CCH + c];
        }
        p = fmaxf(s1, 0.f) * fmaxf(s2, 0.f);
    }
    #pragma unroll
    for (int off = 16; off; off >>= 1) p += __shfl_xor_sync(0xffffffffu, p, off);
    if (j == 0) out[b] = p;
}

// ---------------- host ----------------
extern "C" void kernel_launch(void* const* d_in, const int* in_sizes, int n_in,
                              void* d_out, int out_size) {
    static bool attr_set = false;
    if (!attr_set) {
        cudaFuncSetAttribute(gemm_conv_kernel,
                             cudaFuncAttributeMaxDynamicSharedMemorySize, SMEM_DYN);
        attr_set = true;
    }
    prep_kernel<<<160, 1024>>>((const float*)d_in[2], (const float*)d_in[6]);
    gemm_conv_kernel<<<dim3(NCTA, 2, 2), NTHR, SMEM_DYN>>>(
        (const float*)d_in[0], (const float*)d_in[1],
        (const float*)d_in[3], (const float*)d_in[7]);
    finish_kernel<<<BSZ / 8, 256>>>((const float*)d_in[4], (const float*)d_in[5],
                                    (const float*)d_in[8], (const float*)d_in[9],
                                    (float*)d_out);
}